// round 1
// baseline (speedup 1.0000x reference)
#include <cuda_runtime.h>
#include <math.h>

#define D_MODEL 512
#define N_EXP   8
#define HIDDEN  2048
#define T_MAX   8192
#define MAX_TILES (T_MAX/64 + N_EXP)

// ---------------- scratch (device globals, no allocation) ----------------
__device__ float  g_h[(size_t)T_MAX * HIDDEN];   // 64 MB intermediate (perm order)
__device__ int    g_perm[T_MAX];                 // tile-row -> token id
__device__ int    g_tok_exp[T_MAX];              // token -> expert
__device__ float  g_wsel[T_MAX];                 // token -> (1-y)+y weight
__device__ double g_imp[N_EXP];                  // importance sums (fp64 accum)
__device__ int    g_tile_exp[MAX_TILES];
__device__ int    g_tile_row0[MAX_TILES];
__device__ int    g_tile_rows[MAX_TILES];
__device__ int    g_ntiles;

__device__ __forceinline__ float gelu_exact(float v) {
    return 0.5f * v * (1.0f + erff(v * 0.70710678118654752440f));
}

// ---------------- kernel 0: zero accumulators ----------------
__global__ void init_kernel() {
    if (threadIdx.x < N_EXP) g_imp[threadIdx.x] = 0.0;
}

// ---------------- kernel 1: router (one warp per token) ----------------
__global__ void __launch_bounds__(256) router_kernel(
    const float* __restrict__ x, const float* __restrict__ u,
    const float* __restrict__ rw, const float* __restrict__ rb, int T)
{
    __shared__ float s_imp[N_EXP];
    if (threadIdx.x < N_EXP) s_imp[threadIdx.x] = 0.0f;
    __syncthreads();

    int t    = blockIdx.x * 8 + (threadIdx.x >> 5);
    int lane = threadIdx.x & 31;

    if (t < T) {
        float acc[8];
        #pragma unroll
        for (int e = 0; e < 8; e++) acc[e] = 0.0f;
        const float* xr = x + (size_t)t * D_MODEL;
        for (int k = lane; k < D_MODEL; k += 32) {
            float xv = xr[k];
            float4 wa = *(const float4*)(rw + k * 8);
            float4 wb = *(const float4*)(rw + k * 8 + 4);
            acc[0] += xv * wa.x; acc[1] += xv * wa.y;
            acc[2] += xv * wa.z; acc[3] += xv * wa.w;
            acc[4] += xv * wb.x; acc[5] += xv * wb.y;
            acc[6] += xv * wb.z; acc[7] += xv * wb.w;
        }
        #pragma unroll
        for (int e = 0; e < 8; e++) {
            #pragma unroll
            for (int off = 16; off > 0; off >>= 1)
                acc[e] += __shfl_down_sync(0xffffffffu, acc[e], off);
        }
        if (lane == 0) {
            float logits[8];
            #pragma unroll
            for (int e = 0; e < 8; e++) logits[e] = acc[e] + rb[e];

            // probs = softmax(logits) for aux loss
            float m = logits[0];
            #pragma unroll
            for (int e = 1; e < 8; e++) m = fmaxf(m, logits[e]);
            float p[8]; float se = 0.0f;
            #pragma unroll
            for (int e = 0; e < 8; e++) { p[e] = expf(logits[e] - m); se += p[e]; }
            float inv = 1.0f / se;
            #pragma unroll
            for (int e = 0; e < 8; e++) atomicAdd(&s_imp[e], p[e] * inv);

            // gumbel-softmax hard selection
            const float* ur = u + (size_t)t * 8;
            float z[8];
            int best = 0; float zb = -1e30f;
            #pragma unroll
            for (int e = 0; e < 8; e++) {
                float g = -logf(-logf(ur[e]) + 1e-10f);
                z[e] = logits[e] + g;
                if (z[e] > zb) { zb = z[e]; best = e; }  // first-max like jnp.argmax
            }
            float s2 = 0.0f;
            #pragma unroll
            for (int e = 0; e < 8; e++) s2 += expf(z[e] - zb);
            float y = 1.0f / s2;               // y_soft at argmax
            g_tok_exp[t] = best;
            g_wsel[t]    = (1.0f - y) + y;     // matches hard - sg(y) + y exactly
        }
    }
    __syncthreads();
    if (threadIdx.x < N_EXP)
        atomicAdd(&g_imp[threadIdx.x], (double)s_imp[threadIdx.x]);
}

// ---------------- kernel 2: counting-sort scatter + tile table ----------------
__global__ void scatter_kernel(int T) {
    __shared__ int s_cnt[N_EXP];
    __shared__ int s_run[N_EXP];
    int tid = threadIdx.x;
    if (tid < N_EXP) s_cnt[tid] = 0;
    __syncthreads();
    for (int t = tid; t < T; t += blockDim.x)
        atomicAdd(&s_cnt[g_tok_exp[t]], 1);
    __syncthreads();
    if (tid == 0) {
        int off = 0, nt = 0;
        for (int e = 0; e < N_EXP; e++) {
            int c = s_cnt[e];
            s_run[e] = off;
            for (int m = 0; m < c; m += 64) {
                g_tile_exp[nt]  = e;
                g_tile_row0[nt] = off + m;
                g_tile_rows[nt] = min(64, c - m);
                nt++;
            }
            off += c;
        }
        g_ntiles = nt;
    }
    __syncthreads();
    for (int t = tid; t < T; t += blockDim.x) {
        int pos = atomicAdd(&s_run[g_tok_exp[t]], 1);
        g_perm[pos] = t;
    }
}

// ---------------- kernel 3: grouped GEMM1 (x @ w1 + b1 -> gelu -> g_h) ----------------
// 64x64 tile, K=512, 256 threads, 4x4 per thread
__global__ void __launch_bounds__(256) ffn1_kernel(
    const float* __restrict__ x, const float* __restrict__ w1,
    const float* __restrict__ b1)
{
    int tile = blockIdx.y;
    if (tile >= g_ntiles) return;
    int e    = g_tile_exp[tile];
    int row0 = g_tile_row0[tile];
    int rows = g_tile_rows[tile];
    int n0   = blockIdx.x * 64;

    __shared__ float As[16][68];
    __shared__ float Bs[16][68];
    __shared__ int   s_tok[64];

    int tid = threadIdx.x;
    if (tid < 64) s_tok[tid] = g_perm[row0 + min(tid, rows - 1)];
    __syncthreads();

    int ar = tid >> 2, aseg = tid & 3;      // A loader: row 0..63, seg 0..3
    int br = tid >> 4, bseg = tid & 15;     // B loader: k-row 0..15, seg 0..15
    int tx = tid & 15, ty = tid >> 4;       // compute: n-group, m-group

    const float* wbase = w1 + (size_t)e * D_MODEL * HIDDEN + n0;

    float acc[4][4];
    #pragma unroll
    for (int i = 0; i < 4; i++)
        #pragma unroll
        for (int j = 0; j < 4; j++) acc[i][j] = 0.0f;

    for (int k0 = 0; k0 < D_MODEL; k0 += 16) {
        float4 av = *(const float4*)(x + (size_t)s_tok[ar] * D_MODEL + k0 + aseg * 4);
        As[aseg * 4 + 0][ar] = av.x;
        As[aseg * 4 + 1][ar] = av.y;
        As[aseg * 4 + 2][ar] = av.z;
        As[aseg * 4 + 3][ar] = av.w;
        *(float4*)&Bs[br][bseg * 4] =
            *(const float4*)(wbase + (size_t)(k0 + br) * HIDDEN + bseg * 4);
        __syncthreads();
        #pragma unroll
        for (int kk = 0; kk < 16; kk++) {
            float4 a = *(const float4*)&As[kk][ty * 4];
            float4 b = *(const float4*)&Bs[kk][tx * 4];
            acc[0][0] += a.x * b.x; acc[0][1] += a.x * b.y; acc[0][2] += a.x * b.z; acc[0][3] += a.x * b.w;
            acc[1][0] += a.y * b.x; acc[1][1] += a.y * b.y; acc[1][2] += a.y * b.z; acc[1][3] += a.y * b.w;
            acc[2][0] += a.z * b.x; acc[2][1] += a.z * b.y; acc[2][2] += a.z * b.z; acc[2][3] += a.z * b.w;
            acc[3][0] += a.w * b.x; acc[3][1] += a.w * b.y; acc[3][2] += a.w * b.z; acc[3][3] += a.w * b.w;
        }
        __syncthreads();
    }

    const float* b1r = b1 + (size_t)e * HIDDEN + n0 + tx * 4;
    #pragma unroll
    for (int i = 0; i < 4; i++) {
        int m = ty * 4 + i;
        if (m < rows) {
            float4 v;
            v.x = gelu_exact(acc[i][0] + b1r[0]);
            v.y = gelu_exact(acc[i][1] + b1r[1]);
            v.z = gelu_exact(acc[i][2] + b1r[2]);
            v.w = gelu_exact(acc[i][3] + b1r[3]);
            *(float4*)(g_h + (size_t)(row0 + m) * HIDDEN + n0 + tx * 4) = v;
        }
    }
}

// ---------------- kernel 4: grouped GEMM2 (g_h @ w2 + b2, scale, scatter) ----------------
__global__ void __launch_bounds__(256) ffn2_kernel(
    const float* __restrict__ w2, const float* __restrict__ b2,
    float* __restrict__ out)
{
    int tile = blockIdx.y;
    if (tile >= g_ntiles) return;
    int e    = g_tile_exp[tile];
    int row0 = g_tile_row0[tile];
    int rows = g_tile_rows[tile];
    int n0   = blockIdx.x * 64;

    __shared__ float As[16][68];
    __shared__ float Bs[16][68];
    __shared__ int   s_tok[64];

    int tid = threadIdx.x;
    if (tid < 64) s_tok[tid] = g_perm[row0 + min(tid, rows - 1)];

    int ar = tid >> 2, aseg = tid & 3;
    int br = tid >> 4, bseg = tid & 15;
    int tx = tid & 15, ty = tid >> 4;

    int arow = row0 + min(ar, rows - 1);   // clamp to avoid OOB on last tile
    const float* wbase = w2 + (size_t)e * HIDDEN * D_MODEL + n0;

    float acc[4][4];
    #pragma unroll
    for (int i = 0; i < 4; i++)
        #pragma unroll
        for (int j = 0; j < 4; j++) acc[i][j] = 0.0f;

    __syncthreads();  // covers s_tok before first smem reuse

    for (int k0 = 0; k0 < HIDDEN; k0 += 16) {
        float4 av = *(const float4*)(g_h + (size_t)arow * HIDDEN + k0 + aseg * 4);
        As[aseg * 4 + 0][ar] = av.x;
        As[aseg * 4 + 1][ar] = av.y;
        As[aseg * 4 + 2][ar] = av.z;
        As[aseg * 4 + 3][ar] = av.w;
        *(float4*)&Bs[br][bseg * 4] =
            *(const float4*)(wbase + (size_t)(k0 + br) * D_MODEL + bseg * 4);
        __syncthreads();
        #pragma unroll
        for (int kk = 0; kk < 16; kk++) {
            float4 a = *(const float4*)&As[kk][ty * 4];
            float4 b = *(const float4*)&Bs[kk][tx * 4];
            acc[0][0] += a.x * b.x; acc[0][1] += a.x * b.y; acc[0][2] += a.x * b.z; acc[0][3] += a.x * b.w;
            acc[1][0] += a.y * b.x; acc[1][1] += a.y * b.y; acc[1][2] += a.y * b.z; acc[1][3] += a.y * b.w;
            acc[2][0] += a.z * b.x; acc[2][1] += a.z * b.y; acc[2][2] += a.z * b.z; acc[2][3] += a.z * b.w;
            acc[3][0] += a.w * b.x; acc[3][1] += a.w * b.y; acc[3][2] += a.w * b.z; acc[3][3] += a.w * b.w;
        }
        __syncthreads();
    }

    const float* b2r = b2 + (size_t)e * D_MODEL + n0 + tx * 4;
    #pragma unroll
    for (int i = 0; i < 4; i++) {
        int m = ty * 4 + i;
        if (m < rows) {
            int tok = s_tok[m];
            float w = g_wsel[tok];
            float4 v;
            v.x = w * (acc[i][0] + b2r[0]);
            v.y = w * (acc[i][1] + b2r[1]);
            v.z = w * (acc[i][2] + b2r[2]);
            v.w = w * (acc[i][3] + b2r[3]);
            *(float4*)(out + (size_t)tok * D_MODEL + n0 + tx * 4) = v;
        }
    }
}

// ---------------- kernel 5: aux loss ----------------
__global__ void aux_kernel(float* __restrict__ out, int T) {
    if (threadIdx.x == 0 && blockIdx.x == 0) {
        float s = 0.0f;
        #pragma unroll
        for (int e = 0; e < N_EXP; e++) {
            float im = (float)(g_imp[e] / (double)T);
            float d = im - 0.125f;
            s += d * d;
        }
        out[(size_t)T * D_MODEL] = s * (1.0f / 8.0f);
    }
}

// ---------------- launch ----------------
extern "C" void kernel_launch(void* const* d_in, const int* in_sizes, int n_in,
                              void* d_out, int out_size)
{
    const float* x  = (const float*)d_in[0];
    const float* u  = (const float*)d_in[1];
    const float* rw = (const float*)d_in[2];
    const float* rb = (const float*)d_in[3];
    const float* w1 = (const float*)d_in[4];
    const float* b1 = (const float*)d_in[5];
    const float* w2 = (const float*)d_in[6];
    const float* b2 = (const float*)d_in[7];
    float* out = (float*)d_out;

    int T = in_sizes[0] / D_MODEL;   // 8192

    init_kernel<<<1, 32>>>();
    router_kernel<<<T / 8, 256>>>(x, u, rw, rb, T);
    scatter_kernel<<<1, 1024>>>(T);

    dim3 g1(HIDDEN / 64, T / 64 + N_EXP);
    ffn1_kernel<<<g1, 256>>>(x, w1, b1);

    dim3 g2(D_MODEL / 64, T / 64 + N_EXP);
    ffn2_kernel<<<g2, 256>>>(w2, b2, out);

    aux_kernel<<<1, 32>>>(out, T);
}

// round 2
// speedup vs baseline: 1.0981x; 1.0981x over previous
#include <cuda_runtime.h>
#include <math.h>
#include <string.h>

#define D_MODEL 512
#define N_EXP   8
#define HIDDEN  2048
#define T_MAX   8192
#define TILE_M  128
#define MAX_TILES (T_MAX/TILE_M + N_EXP)   // 72

typedef unsigned long long ull;

// ---------------- scratch (device globals, no allocation) ----------------
__device__ float  g_h[(size_t)T_MAX * HIDDEN];   // 64 MB intermediate (perm order)
__device__ int    g_perm[T_MAX];                 // tile-row -> token id
__device__ int    g_tok_exp[T_MAX];              // token -> expert
__device__ float  g_wsel[T_MAX];                 // token -> (1-y)+y weight
__device__ double g_imp[N_EXP];                  // importance sums (fp64 accum)
__device__ int    g_tile_exp[MAX_TILES];
__device__ int    g_tile_row0[MAX_TILES];
__device__ int    g_tile_rows[MAX_TILES];
__device__ int    g_ntiles;

__device__ __forceinline__ float gelu_exact(float v) {
    return 0.5f * v * (1.0f + erff(v * 0.70710678118654752440f));
}

// ---- f32x2 packed-FMA helpers (FFMA2 on sm_103a, PTX-only path) ----
__device__ __forceinline__ ull pack_dup(float x) {
    ull r; asm("mov.b64 %0,{%1,%1};" : "=l"(r) : "f"(x)); return r;
}
__device__ __forceinline__ void fma2(ull& d, ull a, ull b) {
    asm("fma.rn.f32x2 %0,%1,%2,%0;" : "+l"(d) : "l"(a), "l"(b));
}
__device__ __forceinline__ float2 u2f2(ull v) {
    float2 f; memcpy(&f, &v, 8); return f;
}

// ---------------- kernel 0: zero accumulators ----------------
__global__ void init_kernel() {
    if (threadIdx.x < N_EXP) g_imp[threadIdx.x] = 0.0;
}

// ---------------- kernel 1: router (one warp per token) ----------------
__global__ void __launch_bounds__(256) router_kernel(
    const float* __restrict__ x, const float* __restrict__ u,
    const float* __restrict__ rw, const float* __restrict__ rb, int T)
{
    __shared__ float s_imp[N_EXP];
    if (threadIdx.x < N_EXP) s_imp[threadIdx.x] = 0.0f;
    __syncthreads();

    int t    = blockIdx.x * 8 + (threadIdx.x >> 5);
    int lane = threadIdx.x & 31;

    if (t < T) {
        float acc[8];
        #pragma unroll
        for (int e = 0; e < 8; e++) acc[e] = 0.0f;
        const float* xr = x + (size_t)t * D_MODEL;
        for (int k = lane; k < D_MODEL; k += 32) {
            float xv = xr[k];
            float4 wa = *(const float4*)(rw + k * 8);
            float4 wb = *(const float4*)(rw + k * 8 + 4);
            acc[0] += xv * wa.x; acc[1] += xv * wa.y;
            acc[2] += xv * wa.z; acc[3] += xv * wa.w;
            acc[4] += xv * wb.x; acc[5] += xv * wb.y;
            acc[6] += xv * wb.z; acc[7] += xv * wb.w;
        }
        #pragma unroll
        for (int e = 0; e < 8; e++) {
            #pragma unroll
            for (int off = 16; off > 0; off >>= 1)
                acc[e] += __shfl_down_sync(0xffffffffu, acc[e], off);
        }
        if (lane == 0) {
            float logits[8];
            #pragma unroll
            for (int e = 0; e < 8; e++) logits[e] = acc[e] + rb[e];

            float m = logits[0];
            #pragma unroll
            for (int e = 1; e < 8; e++) m = fmaxf(m, logits[e]);
            float p[8]; float se = 0.0f;
            #pragma unroll
            for (int e = 0; e < 8; e++) { p[e] = expf(logits[e] - m); se += p[e]; }
            float inv = 1.0f / se;
            #pragma unroll
            for (int e = 0; e < 8; e++) atomicAdd(&s_imp[e], p[e] * inv);

            const float* ur = u + (size_t)t * 8;
            float z[8];
            int best = 0; float zb = -1e30f;
            #pragma unroll
            for (int e = 0; e < 8; e++) {
                float g = -logf(-logf(ur[e]) + 1e-10f);
                z[e] = logits[e] + g;
                if (z[e] > zb) { zb = z[e]; best = e; }
            }
            float s2 = 0.0f;
            #pragma unroll
            for (int e = 0; e < 8; e++) s2 += expf(z[e] - zb);
            float y = 1.0f / s2;
            g_tok_exp[t] = best;
            g_wsel[t]    = (1.0f - y) + y;
        }
    }
    __syncthreads();
    if (threadIdx.x < N_EXP)
        atomicAdd(&g_imp[threadIdx.x], (double)s_imp[threadIdx.x]);
}

// ---------------- kernel 2: counting-sort scatter + tile table ----------------
__global__ void scatter_kernel(int T) {
    __shared__ int s_cnt[N_EXP];
    __shared__ int s_run[N_EXP];
    int tid = threadIdx.x;
    if (tid < N_EXP) s_cnt[tid] = 0;
    __syncthreads();
    for (int t = tid; t < T; t += blockDim.x)
        atomicAdd(&s_cnt[g_tok_exp[t]], 1);
    __syncthreads();
    if (tid == 0) {
        int off = 0, nt = 0;
        for (int e = 0; e < N_EXP; e++) {
            int c = s_cnt[e];
            s_run[e] = off;
            for (int m = 0; m < c; m += TILE_M) {
                g_tile_exp[nt]  = e;
                g_tile_row0[nt] = off + m;
                g_tile_rows[nt] = min(TILE_M, c - m);
                nt++;
            }
            off += c;
        }
        g_ntiles = nt;
    }
    __syncthreads();
    for (int t = tid; t < T; t += blockDim.x) {
        int pos = atomicAdd(&s_run[g_tok_exp[t]], 1);
        g_perm[pos] = t;
    }
}

// ================= grouped GEMM: 128x128 tile, 8x8/thread, FFMA2 =================
// 256 threads; tx = tid&15 (8 N-cols), ty = tid>>4 (8 M-rows).

// ---------------- kernel 3: FFN1  (gather x -> h = gelu(x@w1+b1)) ----------------
__global__ void __launch_bounds__(256, 2) ffn1_kernel(
    const float* __restrict__ x, const float* __restrict__ w1,
    const float* __restrict__ b1)
{
    int tile = blockIdx.y;
    if (tile >= g_ntiles) return;
    int e    = g_tile_exp[tile];
    int row0 = g_tile_row0[tile];
    int rows = g_tile_rows[tile];
    int n0   = blockIdx.x * 128;

    __shared__ float As[2][16][132];
    __shared__ float Bs[2][16][132];
    __shared__ int   s_tok[128];

    int tid = threadIdx.x;
    if (tid < 128) s_tok[tid] = g_perm[row0 + min(tid, rows - 1)];
    __syncthreads();

    int arow = tid >> 1, ak = (tid & 1) * 8;
    const float* aptr = x + (size_t)s_tok[arow] * D_MODEL + ak;
    int bk = tid >> 4, bcol = (tid & 15) * 8;
    const float* bptr = w1 + (size_t)e * (D_MODEL * HIDDEN) + (size_t)bk * HIDDEN + n0 + bcol;

    int tx = tid & 15, ty = tid >> 4;

    float4 ra0 = *(const float4*)(aptr);
    float4 ra1 = *(const float4*)(aptr + 4);
    float4 rb0 = *(const float4*)(bptr);
    float4 rb1 = *(const float4*)(bptr + 4);

    ull acc[8][4];
    #pragma unroll
    for (int i = 0; i < 8; i++)
        #pragma unroll
        for (int j = 0; j < 4; j++) acc[i][j] = 0ULL;

    const int NC = D_MODEL / 16;   // 32
    for (int c = 0; c < NC; c++) {
        int p = c & 1;
        As[p][ak + 0][arow] = ra0.x; As[p][ak + 1][arow] = ra0.y;
        As[p][ak + 2][arow] = ra0.z; As[p][ak + 3][arow] = ra0.w;
        As[p][ak + 4][arow] = ra1.x; As[p][ak + 5][arow] = ra1.y;
        As[p][ak + 6][arow] = ra1.z; As[p][ak + 7][arow] = ra1.w;
        *(float4*)&Bs[p][bk][bcol]     = rb0;
        *(float4*)&Bs[p][bk][bcol + 4] = rb1;
        __syncthreads();
        if (c + 1 < NC) {
            aptr += 16;
            bptr += (size_t)16 * HIDDEN;
            ra0 = *(const float4*)(aptr);
            ra1 = *(const float4*)(aptr + 4);
            rb0 = *(const float4*)(bptr);
            rb1 = *(const float4*)(bptr + 4);
        }
        #pragma unroll
        for (int kk = 0; kk < 16; kk++) {
            float4 af0 = *(const float4*)&As[p][kk][ty * 8];
            float4 af1 = *(const float4*)&As[p][kk][ty * 8 + 4];
            const ull* bp = (const ull*)&Bs[p][kk][tx * 8];
            ull b0 = bp[0], b1 = bp[1], b2 = bp[2], b3 = bp[3];
            ull a;
            a = pack_dup(af0.x); fma2(acc[0][0],a,b0); fma2(acc[0][1],a,b1); fma2(acc[0][2],a,b2); fma2(acc[0][3],a,b3);
            a = pack_dup(af0.y); fma2(acc[1][0],a,b0); fma2(acc[1][1],a,b1); fma2(acc[1][2],a,b2); fma2(acc[1][3],a,b3);
            a = pack_dup(af0.z); fma2(acc[2][0],a,b0); fma2(acc[2][1],a,b1); fma2(acc[2][2],a,b2); fma2(acc[2][3],a,b3);
            a = pack_dup(af0.w); fma2(acc[3][0],a,b0); fma2(acc[3][1],a,b1); fma2(acc[3][2],a,b2); fma2(acc[3][3],a,b3);
            a = pack_dup(af1.x); fma2(acc[4][0],a,b0); fma2(acc[4][1],a,b1); fma2(acc[4][2],a,b2); fma2(acc[4][3],a,b3);
            a = pack_dup(af1.y); fma2(acc[5][0],a,b0); fma2(acc[5][1],a,b1); fma2(acc[5][2],a,b2); fma2(acc[5][3],a,b3);
            a = pack_dup(af1.z); fma2(acc[6][0],a,b0); fma2(acc[6][1],a,b1); fma2(acc[6][2],a,b2); fma2(acc[6][3],a,b3);
            a = pack_dup(af1.w); fma2(acc[7][0],a,b0); fma2(acc[7][1],a,b1); fma2(acc[7][2],a,b2); fma2(acc[7][3],a,b3);
        }
    }

    const float* bb = b1 + (size_t)e * HIDDEN + n0 + tx * 8;
    float bias[8];
    #pragma unroll
    for (int j = 0; j < 8; j++) bias[j] = bb[j];

    #pragma unroll
    for (int i = 0; i < 8; i++) {
        int m = ty * 8 + i;
        if (m < rows) {
            float r[8];
            #pragma unroll
            for (int j = 0; j < 4; j++) {
                float2 f = u2f2(acc[i][j]);
                r[2*j]   = gelu_exact(f.x + bias[2*j]);
                r[2*j+1] = gelu_exact(f.y + bias[2*j+1]);
            }
            float* op = g_h + (size_t)(row0 + m) * HIDDEN + n0 + tx * 8;
            *(float4*)op       = make_float4(r[0], r[1], r[2], r[3]);
            *(float4*)(op + 4) = make_float4(r[4], r[5], r[6], r[7]);
        }
    }
}

// ---------------- kernel 4: FFN2  (out[tok] = wsel * (h@w2 + b2)) ----------------
__global__ void __launch_bounds__(256, 2) ffn2_kernel(
    const float* __restrict__ w2, const float* __restrict__ b2,
    float* __restrict__ out)
{
    int tile = blockIdx.y;
    if (tile >= g_ntiles) return;
    int e    = g_tile_exp[tile];
    int row0 = g_tile_row0[tile];
    int rows = g_tile_rows[tile];
    int n0   = blockIdx.x * 128;

    __shared__ float As[2][16][132];
    __shared__ float Bs[2][16][132];
    __shared__ int   s_tok[128];

    int tid = threadIdx.x;
    if (tid < 128) s_tok[tid] = g_perm[row0 + min(tid, rows - 1)];

    int arow = tid >> 1, ak = (tid & 1) * 8;
    const float* aptr = g_h + (size_t)(row0 + min(arow, rows - 1)) * HIDDEN + ak;
    int bk = tid >> 4, bcol = (tid & 15) * 8;
    const float* bptr = w2 + (size_t)e * (HIDDEN * D_MODEL) + (size_t)bk * D_MODEL + n0 + bcol;

    int tx = tid & 15, ty = tid >> 4;

    float4 ra0 = *(const float4*)(aptr);
    float4 ra1 = *(const float4*)(aptr + 4);
    float4 rb0 = *(const float4*)(bptr);
    float4 rb1 = *(const float4*)(bptr + 4);

    ull acc[8][4];
    #pragma unroll
    for (int i = 0; i < 8; i++)
        #pragma unroll
        for (int j = 0; j < 4; j++) acc[i][j] = 0ULL;

    const int NC = HIDDEN / 16;   // 128
    for (int c = 0; c < NC; c++) {
        int p = c & 1;
        As[p][ak + 0][arow] = ra0.x; As[p][ak + 1][arow] = ra0.y;
        As[p][ak + 2][arow] = ra0.z; As[p][ak + 3][arow] = ra0.w;
        As[p][ak + 4][arow] = ra1.x; As[p][ak + 5][arow] = ra1.y;
        As[p][ak + 6][arow] = ra1.z; As[p][ak + 7][arow] = ra1.w;
        *(float4*)&Bs[p][bk][bcol]     = rb0;
        *(float4*)&Bs[p][bk][bcol + 4] = rb1;
        __syncthreads();
        if (c + 1 < NC) {
            aptr += 16;
            bptr += (size_t)16 * D_MODEL;
            ra0 = *(const float4*)(aptr);
            ra1 = *(const float4*)(aptr + 4);
            rb0 = *(const float4*)(bptr);
            rb1 = *(const float4*)(bptr + 4);
        }
        #pragma unroll
        for (int kk = 0; kk < 16; kk++) {
            float4 af0 = *(const float4*)&As[p][kk][ty * 8];
            float4 af1 = *(const float4*)&As[p][kk][ty * 8 + 4];
            const ull* bp = (const ull*)&Bs[p][kk][tx * 8];
            ull b0 = bp[0], b1 = bp[1], b2 = bp[2], b3 = bp[3];
            ull a;
            a = pack_dup(af0.x); fma2(acc[0][0],a,b0); fma2(acc[0][1],a,b1); fma2(acc[0][2],a,b2); fma2(acc[0][3],a,b3);
            a = pack_dup(af0.y); fma2(acc[1][0],a,b0); fma2(acc[1][1],a,b1); fma2(acc[1][2],a,b2); fma2(acc[1][3],a,b3);
            a = pack_dup(af0.z); fma2(acc[2][0],a,b0); fma2(acc[2][1],a,b1); fma2(acc[2][2],a,b2); fma2(acc[2][3],a,b3);
            a = pack_dup(af0.w); fma2(acc[3][0],a,b0); fma2(acc[3][1],a,b1); fma2(acc[3][2],a,b2); fma2(acc[3][3],a,b3);
            a = pack_dup(af1.x); fma2(acc[4][0],a,b0); fma2(acc[4][1],a,b1); fma2(acc[4][2],a,b2); fma2(acc[4][3],a,b3);
            a = pack_dup(af1.y); fma2(acc[5][0],a,b0); fma2(acc[5][1],a,b1); fma2(acc[5][2],a,b2); fma2(acc[5][3],a,b3);
            a = pack_dup(af1.z); fma2(acc[6][0],a,b0); fma2(acc[6][1],a,b1); fma2(acc[6][2],a,b2); fma2(acc[6][3],a,b3);
            a = pack_dup(af1.w); fma2(acc[7][0],a,b0); fma2(acc[7][1],a,b1); fma2(acc[7][2],a,b2); fma2(acc[7][3],a,b3);
        }
    }

    const float* bb = b2 + (size_t)e * D_MODEL + n0 + tx * 8;
    float bias[8];
    #pragma unroll
    for (int j = 0; j < 8; j++) bias[j] = bb[j];

    #pragma unroll
    for (int i = 0; i < 8; i++) {
        int m = ty * 8 + i;
        if (m < rows) {
            int tok = s_tok[m];
            float w = g_wsel[tok];
            float r[8];
            #pragma unroll
            for (int j = 0; j < 4; j++) {
                float2 f = u2f2(acc[i][j]);
                r[2*j]   = w * (f.x + bias[2*j]);
                r[2*j+1] = w * (f.y + bias[2*j+1]);
            }
            float* op = out + (size_t)tok * D_MODEL + n0 + tx * 8;
            *(float4*)op       = make_float4(r[0], r[1], r[2], r[3]);
            *(float4*)(op + 4) = make_float4(r[4], r[5], r[6], r[7]);
        }
    }
}

// ---------------- kernel 5: aux loss ----------------
__global__ void aux_kernel(float* __restrict__ out, int T) {
    if (threadIdx.x == 0 && blockIdx.x == 0) {
        float s = 0.0f;
        #pragma unroll
        for (int e = 0; e < N_EXP; e++) {
            float im = (float)(g_imp[e] / (double)T);
            float d = im - 0.125f;
            s += d * d;
        }
        out[(size_t)T * D_MODEL] = s * (1.0f / 8.0f);
    }
}

// ---------------- launch ----------------
extern "C" void kernel_launch(void* const* d_in, const int* in_sizes, int n_in,
                              void* d_out, int out_size)
{
    const float* x  = (const float*)d_in[0];
    const float* u  = (const float*)d_in[1];
    const float* rw = (const float*)d_in[2];
    const float* rb = (const float*)d_in[3];
    const float* w1 = (const float*)d_in[4];
    const float* b1 = (const float*)d_in[5];
    const float* w2 = (const float*)d_in[6];
    const float* b2 = (const float*)d_in[7];
    float* out = (float*)d_out;

    int T = in_sizes[0] / D_MODEL;   // 8192

    init_kernel<<<1, 32>>>();
    router_kernel<<<T / 8, 256>>>(x, u, rw, rb, T);
    scatter_kernel<<<1, 1024>>>(T);

    int max_tiles = T / TILE_M + N_EXP;
    dim3 g1(HIDDEN / 128, max_tiles);
    ffn1_kernel<<<g1, 256>>>(x, w1, b1);

    dim3 g2(D_MODEL / 128, max_tiles);
    ffn2_kernel<<<g2, 256>>>(w2, b2, out);

    aux_kernel<<<1, 32>>>(out, T);
}

// round 6
// speedup vs baseline: 1.6146x; 1.4704x over previous
#include <cuda_runtime.h>
#include <cuda_bf16.h>
#include <math.h>

#define D_MODEL 512
#define N_EXP   8
#define HIDDEN  2048
#define T_MAX   8192
#define TILE_M  128
#define MAX_TILES (T_MAX/TILE_M + N_EXP)

typedef unsigned int u32;
typedef unsigned short u16;

// smem geometry: 4 regions of 128 rows x 32 k-elements, pitch 40 u16 (80B)
#define PITCH_E 40
#define E_AH 0
#define E_AL 5120
#define E_BH 10240
#define E_BL 15360
#define SMEM_E 20480        // u16 elements = 40960 bytes (static smem, < 48K)

// ---------------- scratch (device globals, no allocation) ----------------
__device__ __align__(16) u16 g_xhi[(size_t)T_MAX * D_MODEL];
__device__ __align__(16) u16 g_xlo[(size_t)T_MAX * D_MODEL];
__device__ __align__(16) u16 g_w1hi[(size_t)N_EXP * HIDDEN * D_MODEL]; // [E][H][D] transposed
__device__ __align__(16) u16 g_w1lo[(size_t)N_EXP * HIDDEN * D_MODEL];
__device__ __align__(16) u16 g_w2hi[(size_t)N_EXP * D_MODEL * HIDDEN]; // [E][D][H] transposed
__device__ __align__(16) u16 g_w2lo[(size_t)N_EXP * D_MODEL * HIDDEN];
__device__ __align__(16) u16 g_hhi[(size_t)T_MAX * HIDDEN];
__device__ __align__(16) u16 g_hlo[(size_t)T_MAX * HIDDEN];
__device__ int    g_perm[T_MAX];
__device__ int    g_tok_exp[T_MAX];
__device__ float  g_wsel[T_MAX];
__device__ double g_imp[N_EXP];
__device__ int    g_tile_exp[MAX_TILES];
__device__ int    g_tile_row0[MAX_TILES];
__device__ int    g_tile_rows[MAX_TILES];
__device__ int    g_ntiles;

__device__ __forceinline__ float gelu_exact(float v) {
    return 0.5f * v * (1.0f + erff(v * 0.70710678118654752440f));
}

// mma.sync m16n8k16 bf16 (portable sm_80+ PTX)
#define MMA(ac, a, b0, b1) \
    asm volatile("mma.sync.aligned.m16n8k16.row.col.f32.bf16.bf16.f32 " \
        "{%0,%1,%2,%3},{%4,%5,%6,%7},{%8,%9},{%0,%1,%2,%3};" \
        : "+f"((ac)[0]), "+f"((ac)[1]), "+f"((ac)[2]), "+f"((ac)[3]) \
        : "r"((a)[0]), "r"((a)[1]), "r"((a)[2]), "r"((a)[3]), "r"(b0), "r"(b1))

// ---------------- kernel 0 ----------------
__global__ void init_kernel() {
    if (threadIdx.x < N_EXP) g_imp[threadIdx.x] = 0.0;
}

// ---------------- kernel 1: router ----------------
__global__ void __launch_bounds__(256) router_kernel(
    const float* __restrict__ x, const float* __restrict__ u,
    const float* __restrict__ rw, const float* __restrict__ rb, int T)
{
    __shared__ float s_imp[N_EXP];
    if (threadIdx.x < N_EXP) s_imp[threadIdx.x] = 0.0f;
    __syncthreads();

    int t    = blockIdx.x * 8 + (threadIdx.x >> 5);
    int lane = threadIdx.x & 31;

    if (t < T) {
        float acc[8];
        #pragma unroll
        for (int e = 0; e < 8; e++) acc[e] = 0.0f;
        const float* xr = x + (size_t)t * D_MODEL;
        for (int k = lane; k < D_MODEL; k += 32) {
            float xv = xr[k];
            float4 wa = *(const float4*)(rw + k * 8);
            float4 wb = *(const float4*)(rw + k * 8 + 4);
            acc[0] += xv * wa.x; acc[1] += xv * wa.y;
            acc[2] += xv * wa.z; acc[3] += xv * wa.w;
            acc[4] += xv * wb.x; acc[5] += xv * wb.y;
            acc[6] += xv * wb.z; acc[7] += xv * wb.w;
        }
        #pragma unroll
        for (int e = 0; e < 8; e++) {
            #pragma unroll
            for (int off = 16; off > 0; off >>= 1)
                acc[e] += __shfl_down_sync(0xffffffffu, acc[e], off);
        }
        if (lane == 0) {
            float logits[8];
            #pragma unroll
            for (int e = 0; e < 8; e++) logits[e] = acc[e] + rb[e];
            float m = logits[0];
            #pragma unroll
            for (int e = 1; e < 8; e++) m = fmaxf(m, logits[e]);
            float p[8]; float se = 0.0f;
            #pragma unroll
            for (int e = 0; e < 8; e++) { p[e] = expf(logits[e] - m); se += p[e]; }
            float inv = 1.0f / se;
            #pragma unroll
            for (int e = 0; e < 8; e++) atomicAdd(&s_imp[e], p[e] * inv);

            const float* ur = u + (size_t)t * 8;
            float z[8]; int best = 0; float zb = -1e30f;
            #pragma unroll
            for (int e = 0; e < 8; e++) {
                float g = -logf(-logf(ur[e]) + 1e-10f);
                z[e] = logits[e] + g;
                if (z[e] > zb) { zb = z[e]; best = e; }
            }
            float s2 = 0.0f;
            #pragma unroll
            for (int e = 0; e < 8; e++) s2 += expf(z[e] - zb);
            float y = 1.0f / s2;
            g_tok_exp[t] = best;
            g_wsel[t]    = (1.0f - y) + y;
        }
    }
    __syncthreads();
    if (threadIdx.x < N_EXP)
        atomicAdd(&g_imp[threadIdx.x], (double)s_imp[threadIdx.x]);
}

// ---------------- kernel 2: scatter + tiles ----------------
__global__ void scatter_kernel(int T) {
    __shared__ int s_cnt[N_EXP];
    __shared__ int s_run[N_EXP];
    int tid = threadIdx.x;
    if (tid < N_EXP) s_cnt[tid] = 0;
    __syncthreads();
    for (int t = tid; t < T; t += blockDim.x)
        atomicAdd(&s_cnt[g_tok_exp[t]], 1);
    __syncthreads();
    if (tid == 0) {
        int off = 0, nt = 0;
        for (int e = 0; e < N_EXP; e++) {
            int c = s_cnt[e];
            s_run[e] = off;
            for (int m = 0; m < c; m += TILE_M) {
                g_tile_exp[nt]  = e;
                g_tile_row0[nt] = off + m;
                g_tile_rows[nt] = min(TILE_M, c - m);
                nt++;
            }
            off += c;
        }
        g_ntiles = nt;
    }
    __syncthreads();
    for (int t = tid; t < T; t += blockDim.x) {
        int pos = atomicAdd(&s_run[g_tok_exp[t]], 1);
        g_perm[pos] = t;
    }
}

// ---------------- kernel 2b: gather + hi/lo convert x (perm order) ----------------
// Writes g_xhi/g_xlo DIRECTLY (device globals referenced in device code).
__global__ void __launch_bounds__(256) convx_kernel(const float* __restrict__ x, int T) {
    int idx = blockIdx.x * 256 + threadIdx.x;
    if (idx >= T * (D_MODEL / 4)) return;
    int row  = idx >> 7;
    int col4 = idx & 127;
    int tok  = g_perm[row];
    float4 v = ((const float4*)x)[(size_t)tok * 128 + col4];
    __nv_bfloat16 h0 = __float2bfloat16(v.x), h1 = __float2bfloat16(v.y);
    __nv_bfloat16 h2 = __float2bfloat16(v.z), h3 = __float2bfloat16(v.w);
    ushort4 H, L;
    H.x = __bfloat16_as_ushort(h0); H.y = __bfloat16_as_ushort(h1);
    H.z = __bfloat16_as_ushort(h2); H.w = __bfloat16_as_ushort(h3);
    L.x = __bfloat16_as_ushort(__float2bfloat16(v.x - __bfloat162float(h0)));
    L.y = __bfloat16_as_ushort(__float2bfloat16(v.y - __bfloat162float(h1)));
    L.z = __bfloat16_as_ushort(__float2bfloat16(v.z - __bfloat162float(h2)));
    L.w = __bfloat16_as_ushort(__float2bfloat16(v.w - __bfloat162float(h3)));
    size_t o = (size_t)row * D_MODEL + col4 * 4;
    *(ushort4*)(g_xhi + o) = H;
    *(ushort4*)(g_xlo + o) = L;
}

// ---------------- kernel 2c: transpose + hi/lo convert weights ----------------
// IMPORTANT: destination device globals are referenced INSIDE the kernel
// (never passed as host-side arguments — host symbol != device address).
// src [E][R][C] fp32 -> dst [E][C][R] bf16 hi/lo bits (k-contiguous B for GEMM)
template<int R, int C, int WHICH>   // WHICH: 1 -> g_w1hi/lo, 2 -> g_w2hi/lo
__global__ void __launch_bounds__(256) convT_kernel(const float* __restrict__ src)
{
    __shared__ float tile[32][33];
    int e  = blockIdx.z;
    int c0 = blockIdx.x * 32, r0 = blockIdx.y * 32;
    int tx = threadIdx.x, ty = threadIdx.y;
    #pragma unroll
    for (int i = 0; i < 4; i++) {
        int r = r0 + ty + i * 8;
        tile[ty + i * 8][tx] = src[((size_t)e * R + r) * C + c0 + tx];
    }
    __syncthreads();
    u16* dhi = (WHICH == 1) ? g_w1hi : g_w2hi;
    u16* dlo = (WHICH == 1) ? g_w1lo : g_w2lo;
    #pragma unroll
    for (int i = 0; i < 4; i++) {
        int c = c0 + ty + i * 8;
        int r = r0 + tx;
        float v = tile[tx][ty + i * 8];
        __nv_bfloat16 h = __float2bfloat16(v);
        float lo = v - __bfloat162float(h);
        size_t o = ((size_t)e * C + c) * R + r;
        dhi[o] = __bfloat16_as_ushort(h);
        dlo[o] = __bfloat16_as_ushort(__float2bfloat16(lo));
    }
}

// ---------------- GEMM mainloop: plain ld/st + per-spec LDS fragments ----------------
// CTA tile 128x128, 8 warps (4m x 2n), warp tile 32x64, K-chunk 32.
// aH/aL/bH/bL: per-thread row base pointers (k-contiguous), advance 32 elems/chunk.
__device__ __forceinline__ void run_gemm(
    u16* sm, const u16* aH, const u16* aL, const u16* bH, const u16* bL,
    int NC, int tid, float acc[2][8][4])
{
    int row = tid >> 1;
    int seg = (tid & 1) * 16;
    int l  = tid & 31;
    int wm = (tid >> 5) & 3;
    int wn = (tid >> 5) >> 2;
    int g  = l >> 2;
    int t  = l & 3;

    uint4 f[8];
    #define LDCH(c) do { \
        const uint4* p_; \
        p_ = (const uint4*)(aH + (size_t)(c) * 32); f[0] = p_[0]; f[1] = p_[1]; \
        p_ = (const uint4*)(aL + (size_t)(c) * 32); f[2] = p_[0]; f[3] = p_[1]; \
        p_ = (const uint4*)(bH + (size_t)(c) * 32); f[4] = p_[0]; f[5] = p_[1]; \
        p_ = (const uint4*)(bL + (size_t)(c) * 32); f[6] = p_[0]; f[7] = p_[1]; \
    } while (0)

    LDCH(0);

    for (int c = 0; c < NC; c++) {
        __syncthreads();
        {
            uint4* q;
            q = (uint4*)(sm + E_AH + row * PITCH_E + seg); q[0] = f[0]; q[1] = f[1];
            q = (uint4*)(sm + E_AL + row * PITCH_E + seg); q[0] = f[2]; q[1] = f[3];
            q = (uint4*)(sm + E_BH + row * PITCH_E + seg); q[0] = f[4]; q[1] = f[5];
            q = (uint4*)(sm + E_BL + row * PITCH_E + seg); q[0] = f[6]; q[1] = f[7];
        }
        __syncthreads();
        if (c + 1 < NC) LDCH(c + 1);

        #pragma unroll
        for (int kk = 0; kk < 2; kk++) {
            int kb = kk * 16;
            u32 ah[2][4], al[2][4];
            #pragma unroll
            for (int mf = 0; mf < 2; mf++) {
                int r = wm * 32 + mf * 16 + g;
                const u16* pa = sm + E_AH + r * PITCH_E + kb + t * 2;
                ah[mf][0] = *(const u32*)pa;
                ah[mf][1] = *(const u32*)(pa + 8 * PITCH_E);
                ah[mf][2] = *(const u32*)(pa + 8);
                ah[mf][3] = *(const u32*)(pa + 8 * PITCH_E + 8);
                const u16* pl = sm + E_AL + r * PITCH_E + kb + t * 2;
                al[mf][0] = *(const u32*)pl;
                al[mf][1] = *(const u32*)(pl + 8 * PITCH_E);
                al[mf][2] = *(const u32*)(pl + 8);
                al[mf][3] = *(const u32*)(pl + 8 * PITCH_E + 8);
            }
            #pragma unroll
            for (int nb = 0; nb < 8; nb++) {
                int n = wn * 64 + nb * 8 + g;
                const u16* pb = sm + E_BH + n * PITCH_E + kb + t * 2;
                u32 bh0 = *(const u32*)pb;
                u32 bh1 = *(const u32*)(pb + 8);
                const u16* pbl = sm + E_BL + n * PITCH_E + kb + t * 2;
                u32 bl0 = *(const u32*)pbl;
                u32 bl1 = *(const u32*)(pbl + 8);
                #pragma unroll
                for (int mf = 0; mf < 2; mf++) {
                    MMA(acc[mf][nb], ah[mf], bh0, bh1);
                    MMA(acc[mf][nb], ah[mf], bl0, bl1);
                    MMA(acc[mf][nb], al[mf], bh0, bh1);
                }
            }
        }
    }
    #undef LDCH
}

// ---------------- kernel 3: FFN1 ----------------
__global__ void __launch_bounds__(256, 2) ffn1_kernel(const float* __restrict__ b1)
{
    int tile = blockIdx.y;
    if (tile >= g_ntiles) return;
    int e    = g_tile_exp[tile];
    int row0 = g_tile_row0[tile];
    int rows = g_tile_rows[tile];
    int n0b  = blockIdx.x * 128;

    __shared__ u16 sm[SMEM_E];
    int tid = threadIdx.x;
    int seg = (tid & 1) * 16;

    int arow = row0 + min(tid >> 1, rows - 1);
    const u16* aH = g_xhi + (size_t)arow * D_MODEL + seg;
    const u16* aL = g_xlo + (size_t)arow * D_MODEL + seg;
    size_t boff = ((size_t)e * HIDDEN + n0b + (tid >> 1)) * D_MODEL + seg;
    const u16* bH = g_w1hi + boff;
    const u16* bL = g_w1lo + boff;

    float acc[2][8][4];
    #pragma unroll
    for (int i = 0; i < 2; i++)
        #pragma unroll
        for (int j = 0; j < 8; j++)
            #pragma unroll
            for (int q = 0; q < 4; q++) acc[i][j][q] = 0.0f;

    run_gemm(sm, aH, aL, bH, bL, D_MODEL / 32, tid, acc);

    int l  = tid & 31;
    int wm = (tid >> 5) & 3;
    int wn = (tid >> 5) >> 2;
    int g  = l >> 2;
    int t  = l & 3;
    const float* be = b1 + (size_t)e * HIDDEN + n0b + wn * 64;

    #pragma unroll
    for (int mf = 0; mf < 2; mf++)
        #pragma unroll
        for (int rr = 0; rr < 2; rr++) {
            int m = wm * 32 + mf * 16 + g + rr * 8;
            if (m < rows) {
                size_t ro = (size_t)(row0 + m) * HIDDEN + n0b + wn * 64;
                #pragma unroll
                for (int nb = 0; nb < 8; nb++) {
                    int nc = nb * 8 + t * 2;
                    float2 bb = *(const float2*)(be + nc);
                    float f0 = gelu_exact(acc[mf][nb][rr * 2 + 0] + bb.x);
                    float f1 = gelu_exact(acc[mf][nb][rr * 2 + 1] + bb.y);
                    __nv_bfloat16 h0 = __float2bfloat16(f0);
                    __nv_bfloat16 h1 = __float2bfloat16(f1);
                    u32 hp = (u32)__bfloat16_as_ushort(h0) | ((u32)__bfloat16_as_ushort(h1) << 16);
                    u16 l0 = __bfloat16_as_ushort(__float2bfloat16(f0 - __bfloat162float(h0)));
                    u16 l1 = __bfloat16_as_ushort(__float2bfloat16(f1 - __bfloat162float(h1)));
                    u32 lp = (u32)l0 | ((u32)l1 << 16);
                    *(u32*)(g_hhi + ro + nc) = hp;
                    *(u32*)(g_hlo + ro + nc) = lp;
                }
            }
        }
}

// ---------------- kernel 4: FFN2 ----------------
__global__ void __launch_bounds__(256, 2) ffn2_kernel(
    const float* __restrict__ b2, float* __restrict__ out)
{
    int tile = blockIdx.y;
    if (tile >= g_ntiles) return;
    int e    = g_tile_exp[tile];
    int row0 = g_tile_row0[tile];
    int rows = g_tile_rows[tile];
    int n0b  = blockIdx.x * 128;

    __shared__ u16 sm[SMEM_E];
    int tid = threadIdx.x;
    int seg = (tid & 1) * 16;

    int arow = row0 + min(tid >> 1, rows - 1);
    const u16* aH = g_hhi + (size_t)arow * HIDDEN + seg;
    const u16* aL = g_hlo + (size_t)arow * HIDDEN + seg;
    size_t boff = ((size_t)e * D_MODEL + n0b + (tid >> 1)) * HIDDEN + seg;
    const u16* bH = g_w2hi + boff;
    const u16* bL = g_w2lo + boff;

    float acc[2][8][4];
    #pragma unroll
    for (int i = 0; i < 2; i++)
        #pragma unroll
        for (int j = 0; j < 8; j++)
            #pragma unroll
            for (int q = 0; q < 4; q++) acc[i][j][q] = 0.0f;

    run_gemm(sm, aH, aL, bH, bL, HIDDEN / 32, tid, acc);

    int l  = tid & 31;
    int wm = (tid >> 5) & 3;
    int wn = (tid >> 5) >> 2;
    int g  = l >> 2;
    int t  = l & 3;
    const float* be = b2 + (size_t)e * D_MODEL + n0b + wn * 64;

    #pragma unroll
    for (int mf = 0; mf < 2; mf++)
        #pragma unroll
        for (int rr = 0; rr < 2; rr++) {
            int m = wm * 32 + mf * 16 + g + rr * 8;
            if (m < rows) {
                int tok = g_perm[row0 + m];
                float w = g_wsel[tok];
                float* ob = out + (size_t)tok * D_MODEL + n0b + wn * 64;
                #pragma unroll
                for (int nb = 0; nb < 8; nb++) {
                    int nc = nb * 8 + t * 2;
                    float2 bb = *(const float2*)(be + nc);
                    float2 v;
                    v.x = w * (acc[mf][nb][rr * 2 + 0] + bb.x);
                    v.y = w * (acc[mf][nb][rr * 2 + 1] + bb.y);
                    *(float2*)(ob + nc) = v;
                }
            }
        }
}

// ---------------- kernel 5: aux loss ----------------
__global__ void aux_kernel(float* __restrict__ out, int T) {
    if (threadIdx.x == 0 && blockIdx.x == 0) {
        float s = 0.0f;
        #pragma unroll
        for (int e = 0; e < N_EXP; e++) {
            float im = (float)(g_imp[e] / (double)T);
            float d = im - 0.125f;
            s += d * d;
        }
        out[(size_t)T * D_MODEL] = s * (1.0f / 8.0f);
    }
}

// ---------------- launch ----------------
extern "C" void kernel_launch(void* const* d_in, const int* in_sizes, int n_in,
                              void* d_out, int out_size)
{
    const float* x  = (const float*)d_in[0];
    const float* u  = (const float*)d_in[1];
    const float* rw = (const float*)d_in[2];
    const float* rb = (const float*)d_in[3];
    const float* w1 = (const float*)d_in[4];
    const float* b1 = (const float*)d_in[5];
    const float* w2 = (const float*)d_in[6];
    const float* b2 = (const float*)d_in[7];
    float* out = (float*)d_out;

    int T = in_sizes[0] / D_MODEL;   // 8192

    init_kernel<<<1, 32>>>();
    router_kernel<<<T / 8, 256>>>(x, u, rw, rb, T);
    scatter_kernel<<<1, 1024>>>(T);
    convx_kernel<<<(T * 128 + 255) / 256, 256>>>(x, T);

    dim3 cb(32, 8);
    convT_kernel<D_MODEL, HIDDEN, 1><<<dim3(HIDDEN / 32, D_MODEL / 32, N_EXP), cb>>>(w1);
    convT_kernel<HIDDEN, D_MODEL, 2><<<dim3(D_MODEL / 32, HIDDEN / 32, N_EXP), cb>>>(w2);

    int max_tiles = T / TILE_M + N_EXP;
    ffn1_kernel<<<dim3(HIDDEN / 128, max_tiles), 256>>>(b1);
    ffn2_kernel<<<dim3(D_MODEL / 128, max_tiles), 256>>>(b2, out);

    aux_kernel<<<1, 32>>>(out, T);
}

// round 7
// speedup vs baseline: 2.1162x; 1.3107x over previous
#include <cuda_runtime.h>
#include <cuda_bf16.h>
#include <math.h>

#define D_MODEL 512
#define N_EXP   8
#define HIDDEN  2048
#define T_MAX   8192
#define TILE_M  128
#define MAX_TILES (T_MAX/TILE_M + N_EXP)

typedef unsigned int u32;
typedef unsigned short u16;

// per-buffer byte layout: 4 regions of 128 rows x 32 u16, pitch 40 u16 (80 B)
#define PITCH_B 80
#define R_AH 0
#define R_AL 10240
#define R_BH 20480
#define R_BL 30720
#define BUF_B 40960
#define SMEM_TOT (2 * BUF_B)   // 81920 B, double buffered

// ---------------- scratch (device globals, no allocation) ----------------
__device__ __align__(16) u16 g_xhi[(size_t)T_MAX * D_MODEL];
__device__ __align__(16) u16 g_xlo[(size_t)T_MAX * D_MODEL];
__device__ __align__(16) u16 g_w1hi[(size_t)N_EXP * HIDDEN * D_MODEL]; // [E][H][D] transposed
__device__ __align__(16) u16 g_w1lo[(size_t)N_EXP * HIDDEN * D_MODEL];
__device__ __align__(16) u16 g_w2hi[(size_t)N_EXP * D_MODEL * HIDDEN]; // [E][D][H] transposed
__device__ __align__(16) u16 g_w2lo[(size_t)N_EXP * D_MODEL * HIDDEN];
__device__ __align__(16) u16 g_hhi[(size_t)T_MAX * HIDDEN];
__device__ __align__(16) u16 g_hlo[(size_t)T_MAX * HIDDEN];
__device__ int    g_perm[T_MAX];
__device__ int    g_tok_exp[T_MAX];
__device__ float  g_wsel[T_MAX];
__device__ double g_imp[N_EXP];
__device__ int    g_tile_exp[MAX_TILES];
__device__ int    g_tile_row0[MAX_TILES];
__device__ int    g_tile_rows[MAX_TILES];
__device__ int    g_ntiles;

__device__ __forceinline__ float gelu_exact(float v) {
    return 0.5f * v * (1.0f + erff(v * 0.70710678118654752440f));
}
__device__ __forceinline__ u32 smem_u32(const void* p) {
    u32 a;
    asm("{ .reg .u64 t; cvta.to.shared.u64 t, %1; cvt.u32.u64 %0, t; }" : "=r"(a) : "l"(p));
    return a;
}

// ---- portable PTX (sm_80+): cp.async, ldmatrix, mma ----
#define CP16(d, s)  asm volatile("cp.async.cg.shared.global [%0], [%1], 16;" :: "r"(d), "l"(s))
#define CPCOMMIT()  asm volatile("cp.async.commit_group;" ::: "memory")
#define CPWAIT1()   asm volatile("cp.async.wait_group 1;" ::: "memory")
#define CPWAIT0()   asm volatile("cp.async.wait_group 0;" ::: "memory")

#define LDM4(r, a) \
    asm volatile("ldmatrix.sync.aligned.m8n8.x4.shared.b16 {%0,%1,%2,%3}, [%4];" \
        : "=r"((r)[0]), "=r"((r)[1]), "=r"((r)[2]), "=r"((r)[3]) : "r"(a))

#define MMA(ac, a0, a1, a2, a3, b0, b1) \
    asm volatile("mma.sync.aligned.m16n8k16.row.col.f32.bf16.bf16.f32 " \
        "{%0,%1,%2,%3},{%4,%5,%6,%7},{%8,%9},{%0,%1,%2,%3};" \
        : "+f"((ac)[0]), "+f"((ac)[1]), "+f"((ac)[2]), "+f"((ac)[3]) \
        : "r"(a0), "r"(a1), "r"(a2), "r"(a3), "r"(b0), "r"(b1))

// ---------------- kernel 0 ----------------
__global__ void init_kernel() {
    if (threadIdx.x < N_EXP) g_imp[threadIdx.x] = 0.0;
}

// ---------------- kernel 1: router ----------------
__global__ void __launch_bounds__(256) router_kernel(
    const float* __restrict__ x, const float* __restrict__ u,
    const float* __restrict__ rw, const float* __restrict__ rb, int T)
{
    __shared__ float s_imp[N_EXP];
    if (threadIdx.x < N_EXP) s_imp[threadIdx.x] = 0.0f;
    __syncthreads();

    int t    = blockIdx.x * 8 + (threadIdx.x >> 5);
    int lane = threadIdx.x & 31;

    if (t < T) {
        float acc[8];
        #pragma unroll
        for (int e = 0; e < 8; e++) acc[e] = 0.0f;
        const float* xr = x + (size_t)t * D_MODEL;
        for (int k = lane; k < D_MODEL; k += 32) {
            float xv = xr[k];
            float4 wa = *(const float4*)(rw + k * 8);
            float4 wb = *(const float4*)(rw + k * 8 + 4);
            acc[0] += xv * wa.x; acc[1] += xv * wa.y;
            acc[2] += xv * wa.z; acc[3] += xv * wa.w;
            acc[4] += xv * wb.x; acc[5] += xv * wb.y;
            acc[6] += xv * wb.z; acc[7] += xv * wb.w;
        }
        #pragma unroll
        for (int e = 0; e < 8; e++) {
            #pragma unroll
            for (int off = 16; off > 0; off >>= 1)
                acc[e] += __shfl_down_sync(0xffffffffu, acc[e], off);
        }
        if (lane == 0) {
            float logits[8];
            #pragma unroll
            for (int e = 0; e < 8; e++) logits[e] = acc[e] + rb[e];
            float m = logits[0];
            #pragma unroll
            for (int e = 1; e < 8; e++) m = fmaxf(m, logits[e]);
            float p[8]; float se = 0.0f;
            #pragma unroll
            for (int e = 0; e < 8; e++) { p[e] = expf(logits[e] - m); se += p[e]; }
            float inv = 1.0f / se;
            #pragma unroll
            for (int e = 0; e < 8; e++) atomicAdd(&s_imp[e], p[e] * inv);

            const float* ur = u + (size_t)t * 8;
            float z[8]; int best = 0; float zb = -1e30f;
            #pragma unroll
            for (int e = 0; e < 8; e++) {
                float g = -logf(-logf(ur[e]) + 1e-10f);
                z[e] = logits[e] + g;
                if (z[e] > zb) { zb = z[e]; best = e; }
            }
            float s2 = 0.0f;
            #pragma unroll
            for (int e = 0; e < 8; e++) s2 += expf(z[e] - zb);
            float y = 1.0f / s2;
            g_tok_exp[t] = best;
            g_wsel[t]    = (1.0f - y) + y;
        }
    }
    __syncthreads();
    if (threadIdx.x < N_EXP)
        atomicAdd(&g_imp[threadIdx.x], (double)s_imp[threadIdx.x]);
}

// ---------------- kernel 2: scatter + tiles ----------------
__global__ void scatter_kernel(int T) {
    __shared__ int s_cnt[N_EXP];
    __shared__ int s_run[N_EXP];
    int tid = threadIdx.x;
    if (tid < N_EXP) s_cnt[tid] = 0;
    __syncthreads();
    for (int t = tid; t < T; t += blockDim.x)
        atomicAdd(&s_cnt[g_tok_exp[t]], 1);
    __syncthreads();
    if (tid == 0) {
        int off = 0, nt = 0;
        for (int e = 0; e < N_EXP; e++) {
            int c = s_cnt[e];
            s_run[e] = off;
            for (int m = 0; m < c; m += TILE_M) {
                g_tile_exp[nt]  = e;
                g_tile_row0[nt] = off + m;
                g_tile_rows[nt] = min(TILE_M, c - m);
                nt++;
            }
            off += c;
        }
        g_ntiles = nt;
    }
    __syncthreads();
    for (int t = tid; t < T; t += blockDim.x) {
        int pos = atomicAdd(&s_run[g_tok_exp[t]], 1);
        g_perm[pos] = t;
    }
}

// ---------------- kernel 2b: gather + hi/lo convert x (perm order) ----------------
__global__ void __launch_bounds__(256) convx_kernel(const float* __restrict__ x, int T) {
    int idx = blockIdx.x * 256 + threadIdx.x;
    if (idx >= T * (D_MODEL / 4)) return;
    int row  = idx >> 7;
    int col4 = idx & 127;
    int tok  = g_perm[row];
    float4 v = ((const float4*)x)[(size_t)tok * 128 + col4];
    __nv_bfloat16 h0 = __float2bfloat16(v.x), h1 = __float2bfloat16(v.y);
    __nv_bfloat16 h2 = __float2bfloat16(v.z), h3 = __float2bfloat16(v.w);
    ushort4 H, L;
    H.x = __bfloat16_as_ushort(h0); H.y = __bfloat16_as_ushort(h1);
    H.z = __bfloat16_as_ushort(h2); H.w = __bfloat16_as_ushort(h3);
    L.x = __bfloat16_as_ushort(__float2bfloat16(v.x - __bfloat162float(h0)));
    L.y = __bfloat16_as_ushort(__float2bfloat16(v.y - __bfloat162float(h1)));
    L.z = __bfloat16_as_ushort(__float2bfloat16(v.z - __bfloat162float(h2)));
    L.w = __bfloat16_as_ushort(__float2bfloat16(v.w - __bfloat162float(h3)));
    size_t o = (size_t)row * D_MODEL + col4 * 4;
    *(ushort4*)(g_xhi + o) = H;
    *(ushort4*)(g_xlo + o) = L;
}

// ---------------- kernel 2c: transpose + hi/lo convert weights ----------------
// Destination device globals referenced INSIDE the kernel (host symbol != device addr).
template<int R, int C, int WHICH>
__global__ void __launch_bounds__(256) convT_kernel(const float* __restrict__ src)
{
    __shared__ float tile[32][33];
    int e  = blockIdx.z;
    int c0 = blockIdx.x * 32, r0 = blockIdx.y * 32;
    int tx = threadIdx.x, ty = threadIdx.y;
    #pragma unroll
    for (int i = 0; i < 4; i++) {
        int r = r0 + ty + i * 8;
        tile[ty + i * 8][tx] = src[((size_t)e * R + r) * C + c0 + tx];
    }
    __syncthreads();
    u16* dhi = (WHICH == 1) ? g_w1hi : g_w2hi;
    u16* dlo = (WHICH == 1) ? g_w1lo : g_w2lo;
    #pragma unroll
    for (int i = 0; i < 4; i++) {
        int c = c0 + ty + i * 8;
        int r = r0 + tx;
        float v = tile[tx][ty + i * 8];
        __nv_bfloat16 h = __float2bfloat16(v);
        float lo = v - __bfloat162float(h);
        size_t o = ((size_t)e * C + c) * R + r;
        dhi[o] = __bfloat16_as_ushort(h);
        dlo[o] = __bfloat16_as_ushort(__float2bfloat16(lo));
    }
}

// ---------------- GEMM mainloop: cp.async double-buffer + ldmatrix ----------------
// CTA tile 128x128, 8 warps (4m x 2n), warp tile 32x64, K-chunk 32.
// aH/aL/bH/bL: per-thread src pointers (base row + seg), advance 32 u16/chunk.
__device__ __forceinline__ void run_gemm(
    u32 sb, const u16* aH, const u16* aL, const u16* bH, const u16* bL,
    int NC, int tid, float acc[2][8][4])
{
    int l  = tid & 31;
    int wm = (tid >> 5) & 3;
    int wn = (tid >> 5) >> 2;

    // cp.async destination (bytes): row = tid>>1 (128 rows), half = (tid&1)*32B
    u32 rowoff = (u32)(tid >> 1) * PITCH_B + (u32)(tid & 1) * 32;

    // ldmatrix lane addressing (bytes within region)
    // A: matrices {m0-7,k0-7},{m8-15,k0-7},{m0-7,k8-15},{m8-15,k8-15}
    u32 a_row = (u32)(wm * 32 + (l & 7) + ((l & 8) ? 8 : 0));
    u32 a_col = (u32)((l & 16) ? 8 : 0);
    // B: per 16-n group p: {n0-7,k0-7},{n0-7,k8-15},{n8-15,k0-7},{n8-15,k8-15}
    u32 b_row = (u32)(wn * 64 + (l & 7) + ((l & 16) ? 8 : 0));
    u32 b_col = (u32)((l & 8) ? 8 : 0);

    #define ISSUE(c, b) do { \
        u32 d_ = sb + (u32)(b) * BUF_B + rowoff; \
        const u16* s_; \
        s_ = aH + (size_t)(c) * 32; CP16(d_ + R_AH, s_); CP16(d_ + R_AH + 16, s_ + 8); \
        s_ = aL + (size_t)(c) * 32; CP16(d_ + R_AL, s_); CP16(d_ + R_AL + 16, s_ + 8); \
        s_ = bH + (size_t)(c) * 32; CP16(d_ + R_BH, s_); CP16(d_ + R_BH + 16, s_ + 8); \
        s_ = bL + (size_t)(c) * 32; CP16(d_ + R_BL, s_); CP16(d_ + R_BL + 16, s_ + 8); \
        CPCOMMIT(); \
    } while (0)

    ISSUE(0, 0);
    if (NC > 1) ISSUE(1, 1);

    for (int c = 0; c < NC; c++) {
        if (c + 1 < NC) { CPWAIT1(); } else { CPWAIT0(); }
        __syncthreads();
        u32 buf = sb + (u32)(c & 1) * BUF_B;

        #pragma unroll
        for (int kk = 0; kk < 2; kk++) {
            u32 kbb = (u32)(kk * 16) * 2;   // k offset in bytes
            u32 ah0[4], ah1[4], al0[4], al1[4];
            u32 aaddr = buf + R_AH + (a_row) * PITCH_B + (a_col) * 2 + kbb;
            LDM4(ah0, aaddr);
            LDM4(ah1, aaddr + 16 * PITCH_B);
            u32 aladdr = aaddr + (R_AL - R_AH);
            LDM4(al0, aladdr);
            LDM4(al1, aladdr + 16 * PITCH_B);

            #pragma unroll
            for (int p = 0; p < 4; p++) {
                u32 bh[4], bl[4];
                u32 baddr = buf + R_BH + (b_row + p * 16) * PITCH_B + (b_col) * 2 + kbb;
                LDM4(bh, baddr);
                LDM4(bl, baddr + (R_BL - R_BH));
                int n0 = p * 2;
                // hi*hi, hi*lo, lo*hi  (3-term split)
                MMA(acc[0][n0],   ah0[0], ah0[1], ah0[2], ah0[3], bh[0], bh[1]);
                MMA(acc[0][n0],   ah0[0], ah0[1], ah0[2], ah0[3], bl[0], bl[1]);
                MMA(acc[0][n0],   al0[0], al0[1], al0[2], al0[3], bh[0], bh[1]);
                MMA(acc[0][n0+1], ah0[0], ah0[1], ah0[2], ah0[3], bh[2], bh[3]);
                MMA(acc[0][n0+1], ah0[0], ah0[1], ah0[2], ah0[3], bl[2], bl[3]);
                MMA(acc[0][n0+1], al0[0], al0[1], al0[2], al0[3], bh[2], bh[3]);
                MMA(acc[1][n0],   ah1[0], ah1[1], ah1[2], ah1[3], bh[0], bh[1]);
                MMA(acc[1][n0],   ah1[0], ah1[1], ah1[2], ah1[3], bl[0], bl[1]);
                MMA(acc[1][n0],   al1[0], al1[1], al1[2], al1[3], bh[0], bh[1]);
                MMA(acc[1][n0+1], ah1[0], ah1[1], ah1[2], ah1[3], bh[2], bh[3]);
                MMA(acc[1][n0+1], ah1[0], ah1[1], ah1[2], ah1[3], bl[2], bl[3]);
                MMA(acc[1][n0+1], al1[0], al1[1], al1[2], al1[3], bh[2], bh[3]);
            }
        }
        __syncthreads();
        if (c + 2 < NC) ISSUE(c + 2, c & 1);
    }
    #undef ISSUE
}

// ---------------- kernel 3: FFN1 ----------------
__global__ void __launch_bounds__(256, 2) ffn1_kernel(const float* __restrict__ b1)
{
    int tile = blockIdx.y;
    if (tile >= g_ntiles) return;
    int e    = g_tile_exp[tile];
    int row0 = g_tile_row0[tile];
    int rows = g_tile_rows[tile];
    int n0b  = blockIdx.x * 128;

    extern __shared__ u16 smem_dyn[];
    u32 sb  = smem_u32(smem_dyn);
    int tid = threadIdx.x;
    int seg = (tid & 1) * 16;

    int arow = row0 + min(tid >> 1, rows - 1);
    const u16* aH = g_xhi + (size_t)arow * D_MODEL + seg;
    const u16* aL = g_xlo + (size_t)arow * D_MODEL + seg;
    size_t boff = ((size_t)e * HIDDEN + n0b + (tid >> 1)) * D_MODEL + seg;
    const u16* bH = g_w1hi + boff;
    const u16* bL = g_w1lo + boff;

    float acc[2][8][4];
    #pragma unroll
    for (int i = 0; i < 2; i++)
        #pragma unroll
        for (int j = 0; j < 8; j++)
            #pragma unroll
            for (int q = 0; q < 4; q++) acc[i][j][q] = 0.0f;

    run_gemm(sb, aH, aL, bH, bL, D_MODEL / 32, tid, acc);

    int l  = tid & 31;
    int wm = (tid >> 5) & 3;
    int wn = (tid >> 5) >> 2;
    int g  = l >> 2;
    int t  = l & 3;
    const float* be = b1 + (size_t)e * HIDDEN + n0b + wn * 64;

    #pragma unroll
    for (int mf = 0; mf < 2; mf++)
        #pragma unroll
        for (int rr = 0; rr < 2; rr++) {
            int m = wm * 32 + mf * 16 + g + rr * 8;
            if (m < rows) {
                size_t ro = (size_t)(row0 + m) * HIDDEN + n0b + wn * 64;
                #pragma unroll
                for (int nb = 0; nb < 8; nb++) {
                    int nc = nb * 8 + t * 2;
                    float2 bb = *(const float2*)(be + nc);
                    float f0 = gelu_exact(acc[mf][nb][rr * 2 + 0] + bb.x);
                    float f1 = gelu_exact(acc[mf][nb][rr * 2 + 1] + bb.y);
                    __nv_bfloat16 h0 = __float2bfloat16(f0);
                    __nv_bfloat16 h1 = __float2bfloat16(f1);
                    u32 hp = (u32)__bfloat16_as_ushort(h0) | ((u32)__bfloat16_as_ushort(h1) << 16);
                    u16 l0 = __bfloat16_as_ushort(__float2bfloat16(f0 - __bfloat162float(h0)));
                    u16 l1 = __bfloat16_as_ushort(__float2bfloat16(f1 - __bfloat162float(h1)));
                    u32 lp = (u32)l0 | ((u32)l1 << 16);
                    *(u32*)(g_hhi + ro + nc) = hp;
                    *(u32*)(g_hlo + ro + nc) = lp;
                }
            }
        }
}

// ---------------- kernel 4: FFN2 ----------------
__global__ void __launch_bounds__(256, 2) ffn2_kernel(
    const float* __restrict__ b2, float* __restrict__ out)
{
    int tile = blockIdx.y;
    if (tile >= g_ntiles) return;
    int e    = g_tile_exp[tile];
    int row0 = g_tile_row0[tile];
    int rows = g_tile_rows[tile];
    int n0b  = blockIdx.x * 128;

    extern __shared__ u16 smem_dyn[];
    u32 sb  = smem_u32(smem_dyn);
    int tid = threadIdx.x;
    int seg = (tid & 1) * 16;

    int arow = row0 + min(tid >> 1, rows - 1);
    const u16* aH = g_hhi + (size_t)arow * HIDDEN + seg;
    const u16* aL = g_hlo + (size_t)arow * HIDDEN + seg;
    size_t boff = ((size_t)e * D_MODEL + n0b + (tid >> 1)) * HIDDEN + seg;
    const u16* bH = g_w2hi + boff;
    const u16* bL = g_w2lo + boff;

    float acc[2][8][4];
    #pragma unroll
    for (int i = 0; i < 2; i++)
        #pragma unroll
        for (int j = 0; j < 8; j++)
            #pragma unroll
            for (int q = 0; q < 4; q++) acc[i][j][q] = 0.0f;

    run_gemm(sb, aH, aL, bH, bL, HIDDEN / 32, tid, acc);

    int l  = tid & 31;
    int wm = (tid >> 5) & 3;
    int wn = (tid >> 5) >> 2;
    int g  = l >> 2;
    int t  = l & 3;
    const float* be = b2 + (size_t)e * D_MODEL + n0b + wn * 64;

    #pragma unroll
    for (int mf = 0; mf < 2; mf++)
        #pragma unroll
        for (int rr = 0; rr < 2; rr++) {
            int m = wm * 32 + mf * 16 + g + rr * 8;
            if (m < rows) {
                int tok = g_perm[row0 + m];
                float w = g_wsel[tok];
                float* ob = out + (size_t)tok * D_MODEL + n0b + wn * 64;
                #pragma unroll
                for (int nb = 0; nb < 8; nb++) {
                    int nc = nb * 8 + t * 2;
                    float2 bb = *(const float2*)(be + nc);
                    float2 v;
                    v.x = w * (acc[mf][nb][rr * 2 + 0] + bb.x);
                    v.y = w * (acc[mf][nb][rr * 2 + 1] + bb.y);
                    *(float2*)(ob + nc) = v;
                }
            }
        }
}

// ---------------- kernel 5: aux loss ----------------
__global__ void aux_kernel(float* __restrict__ out, int T) {
    if (threadIdx.x == 0 && blockIdx.x == 0) {
        float s = 0.0f;
        #pragma unroll
        for (int e = 0; e < N_EXP; e++) {
            float im = (float)(g_imp[e] / (double)T);
            float d = im - 0.125f;
            s += d * d;
        }
        out[(size_t)T * D_MODEL] = s * (1.0f / 8.0f);
    }
}

// ---------------- launch ----------------
extern "C" void kernel_launch(void* const* d_in, const int* in_sizes, int n_in,
                              void* d_out, int out_size)
{
    const float* x  = (const float*)d_in[0];
    const float* u  = (const float*)d_in[1];
    const float* rw = (const float*)d_in[2];
    const float* rb = (const float*)d_in[3];
    const float* w1 = (const float*)d_in[4];
    const float* b1 = (const float*)d_in[5];
    const float* w2 = (const float*)d_in[6];
    const float* b2 = (const float*)d_in[7];
    float* out = (float*)d_out;

    int T = in_sizes[0] / D_MODEL;   // 8192

    cudaFuncSetAttribute(ffn1_kernel, cudaFuncAttributeMaxDynamicSharedMemorySize, SMEM_TOT);
    cudaFuncSetAttribute(ffn2_kernel, cudaFuncAttributeMaxDynamicSharedMemorySize, SMEM_TOT);

    init_kernel<<<1, 32>>>();
    router_kernel<<<T / 8, 256>>>(x, u, rw, rb, T);
    scatter_kernel<<<1, 1024>>>(T);
    convx_kernel<<<(T * 128 + 255) / 256, 256>>>(x, T);

    dim3 cb(32, 8);
    convT_kernel<D_MODEL, HIDDEN, 1><<<dim3(HIDDEN / 32, D_MODEL / 32, N_EXP), cb>>>(w1);
    convT_kernel<HIDDEN, D_MODEL, 2><<<dim3(D_MODEL / 32, HIDDEN / 32, N_EXP), cb>>>(w2);

    int max_tiles = T / TILE_M + N_EXP;
    ffn1_kernel<<<dim3(HIDDEN / 128, max_tiles), 256, SMEM_TOT>>>(b1);
    ffn2_kernel<<<dim3(D_MODEL / 128, max_tiles), 256, SMEM_TOT>>>(b2, out);

    aux_kernel<<<1, 32>>>(out, T);
}